// round 7
// baseline (speedup 1.0000x reference)
#include <cuda_runtime.h>
#include <cuda_bf16.h>
#include <math.h>

// Problem constants (fixed by setup_inputs)
#define BATCH   2
#define SEQ     2048
#define DM      1024
#define NH      16
#define HD      64
#define MTOT    (BATCH * SEQ)      // 4096
#define BH      (BATCH * NH)       // 32

// ---------------- scratch (static device globals; no allocs allowed) -------
__device__ float g_Q[(size_t)BH * SEQ * HD];     // [bh][l][hd]
__device__ float g_K[(size_t)BH * SEQ * HD];
__device__ float g_V[(size_t)BH * SEQ * HD];
__device__ float g_attn[(size_t)MTOT * DM];      // [b*l][dm]
__device__ float g_maskbias[MTOT];               // [b][l] -> 0 or -inf

// ================== mask dtype sniff + convert to float bias ===============
// The harness may deliver the bool mask as uint8, int32, or float32. Values
// are only 0/1 (or 0/0xFF). Classify by scanning the first 1024 32-bit words
// (safe for all dtypes: min buffer = 4096 bytes):
//   word == 0x3F800000  -> float32 (1.0f) ; impossible from {0,1} bytes
//   word > 1 (not f32 1)-> packed uint8
//   else                -> int32
__global__ __launch_bounds__(1024) void mask_convert(const void* __restrict__ mask)
{
    __shared__ int s_f32, s_u8;
    const unsigned int* w = (const unsigned int*)mask;
    const int tid = threadIdx.x;
    if (tid == 0) { s_f32 = 0; s_u8 = 0; }
    __syncthreads();
    unsigned int x = w[tid];                 // words 0..1023
    if (x == 0x3F800000u) atomicOr(&s_f32, 1);
    else if (x > 1u)      atomicOr(&s_u8, 1);
    __syncthreads();
    const int cls = s_f32 ? 2 : (s_u8 ? 0 : 1);

#pragma unroll
    for (int u = 0; u < 4; u++) {
        int i = tid * 4 + u;                 // 0..4095
        bool m;
        if (cls == 0)      m = ((const unsigned char*)mask)[i] != 0;
        else if (cls == 1) m = ((const int*)mask)[i] != 0;
        else               m = ((const unsigned int*)mask)[i] != 0u;  // f32 bits
        g_maskbias[i] = m ? -INFINITY : 0.f;
    }
}

// ======================= SGEMM: C = A * B^T + bias =========================
// A: [M=4096, K=1024] row-major, B: [N=1024, K=1024] row-major (weights [out,in])
// permute=1: write to [bh][l][hd] layout (QKV), permute=0: plain [m][n].
#define GM_BM 128
#define GM_BN 128
#define GM_BK 16

__global__ __launch_bounds__(256) void sgemm_abt(
    const float* __restrict__ A, const float* __restrict__ B,
    const float* __restrict__ bias, float* __restrict__ C, int permute)
{
    __shared__ float As[GM_BK][GM_BM];
    __shared__ float Bs[GM_BK][GM_BN];

    const int tid = threadIdx.x;
    const int bm = blockIdx.y * GM_BM;
    const int bn = blockIdx.x * GM_BN;
    const int tx = tid & 15;   // 0..15 -> 8 cols each
    const int ty = tid >> 4;   // 0..15 -> 8 rows each

    float acc[8][8];
#pragma unroll
    for (int i = 0; i < 8; i++)
#pragma unroll
        for (int j = 0; j < 8; j++) acc[i][j] = 0.f;

    for (int k0 = 0; k0 < DM; k0 += GM_BK) {
        // load 128x16 tiles of A and B (as float4), store transposed [k][m]
#pragma unroll
        for (int u = 0; u < 2; u++) {
            int idx = tid + u * 256;          // 0..511
            int row = idx >> 2;               // 0..127
            int c4  = (idx & 3) * 4;          // 0,4,8,12
            float4 av = *(const float4*)(A + (size_t)(bm + row) * DM + k0 + c4);
            As[c4 + 0][row] = av.x; As[c4 + 1][row] = av.y;
            As[c4 + 2][row] = av.z; As[c4 + 3][row] = av.w;
            float4 bv = *(const float4*)(B + (size_t)(bn + row) * DM + k0 + c4);
            Bs[c4 + 0][row] = bv.x; Bs[c4 + 1][row] = bv.y;
            Bs[c4 + 2][row] = bv.z; Bs[c4 + 3][row] = bv.w;
        }
        __syncthreads();

#pragma unroll
        for (int kk = 0; kk < GM_BK; kk++) {
            float a[8], b[8];
            *(float4*)(a)     = *(const float4*)&As[kk][ty * 8];
            *(float4*)(a + 4) = *(const float4*)&As[kk][ty * 8 + 4];
            *(float4*)(b)     = *(const float4*)&Bs[kk][tx * 8];
            *(float4*)(b + 4) = *(const float4*)&Bs[kk][tx * 8 + 4];
#pragma unroll
            for (int i = 0; i < 8; i++)
#pragma unroll
                for (int j = 0; j < 8; j++) acc[i][j] += a[i] * b[j];
        }
        __syncthreads();
    }

    // epilogue
    float bi[8];
#pragma unroll
    for (int j = 0; j < 8; j++) bi[j] = bias[bn + tx * 8 + j];

    if (!permute) {
#pragma unroll
        for (int i = 0; i < 8; i++) {
            int m = bm + ty * 8 + i;
            float4 v0, v1;
            v0.x = acc[i][0] + bi[0]; v0.y = acc[i][1] + bi[1];
            v0.z = acc[i][2] + bi[2]; v0.w = acc[i][3] + bi[3];
            v1.x = acc[i][4] + bi[4]; v1.y = acc[i][5] + bi[5];
            v1.z = acc[i][6] + bi[6]; v1.w = acc[i][7] + bi[7];
            *(float4*)(C + (size_t)m * DM + bn + tx * 8)     = v0;
            *(float4*)(C + (size_t)m * DM + bn + tx * 8 + 4) = v1;
        }
    } else {
#pragma unroll
        for (int i = 0; i < 8; i++) {
            int m = bm + ty * 8 + i;
            int b_ = m >> 11;          // m / 2048
            int l  = m & (SEQ - 1);
#pragma unroll
            for (int j = 0; j < 8; j++) {
                int n = bn + tx * 8 + j;
                int h = n >> 6;        // n / 64
                int d = n & (HD - 1);
                C[((size_t)(b_ * NH + h) * SEQ + l) * HD + d] = acc[i][j] + bi[j];
            }
        }
    }
}

// ======================= Flash attention (fp32) ============================
// Q,K,V: [bh][l][64]. out: [b][l][1024] (head-interleaved).
// grid: (SEQ/64, BH), 128 threads. Thread microtile: 8 q-rows x 4 kv-cols.
#define AT_PAD 68

__global__ __launch_bounds__(128) void attn_kernel(
    const float* __restrict__ Q, const float* __restrict__ K,
    const float* __restrict__ V, const float* __restrict__ maskbias,
    float* __restrict__ out)
{
    __shared__ float Qs[64][AT_PAD];
    __shared__ float Ks[64][AT_PAD];
    __shared__ float Vs[64][AT_PAD];
    __shared__ float Ps[64][AT_PAD];
    __shared__ float Ms[64];

    const int bh = blockIdx.y;
    const int b_ = bh >> 4;
    const int h  = bh & (NH - 1);
    const int q0 = blockIdx.x * 64;
    const int tid = threadIdx.x;
    const int tx = tid & 15;   // col group (4 cols)
    const int ty = tid >> 4;   // row group (8 rows)
    const float scale = 0.125f;   // 1/sqrt(64)

    // load Q tile (64x64)
    const float* Qb = Q + ((size_t)bh * SEQ + q0) * HD;
    for (int i = tid; i < 64 * 64; i += 128) Qs[i >> 6][i & 63] = Qb[i];

    float O[8][4];
    float m_i[8], l_i[8];
#pragma unroll
    for (int r = 0; r < 8; r++) {
        m_i[r] = -INFINITY; l_i[r] = 0.f;
#pragma unroll
        for (int j = 0; j < 4; j++) O[r][j] = 0.f;
    }
    __syncthreads();

    for (int t = 0; t < SEQ / 64; t++) {
        const int k0 = t * 64;
        const float* Kb = K + ((size_t)bh * SEQ + k0) * HD;
        const float* Vb = V + ((size_t)bh * SEQ + k0) * HD;
        for (int i = tid; i < 64 * 64; i += 128) {
            Ks[i >> 6][i & 63] = Kb[i];
            Vs[i >> 6][i & 63] = Vb[i];
        }
        if (tid < 64) Ms[tid] = maskbias[(size_t)b_ * SEQ + k0 + tid];
        __syncthreads();

        // S = Qs * Ks^T (8x4 per thread)
        float S[8][4];
#pragma unroll
        for (int r = 0; r < 8; r++)
#pragma unroll
            for (int c = 0; c < 4; c++) S[r][c] = 0.f;

#pragma unroll 4
        for (int d = 0; d < HD; d += 4) {
            float4 kf[4];
#pragma unroll
            for (int c = 0; c < 4; c++) kf[c] = *(const float4*)&Ks[tx * 4 + c][d];
#pragma unroll
            for (int r = 0; r < 8; r++) {
                float4 qf = *(const float4*)&Qs[ty * 8 + r][d];
#pragma unroll
                for (int c = 0; c < 4; c++) {
                    S[r][c] += qf.x * kf[c].x + qf.y * kf[c].y
                             + qf.z * kf[c].z + qf.w * kf[c].w;
                }
            }
        }

        // scale + mask, rowmax over the 16-lane (tx) group
        float msafe[8], alpha[8], rowsum[8];
#pragma unroll
        for (int r = 0; r < 8; r++) {
            float rm = -INFINITY;
#pragma unroll
            for (int c = 0; c < 4; c++) {
                S[r][c] = S[r][c] * scale + Ms[tx * 4 + c];
                rm = fmaxf(rm, S[r][c]);
            }
#pragma unroll
            for (int off = 8; off >= 1; off >>= 1)
                rm = fmaxf(rm, __shfl_xor_sync(0xffffffffu, rm, off));
            float m_new = fmaxf(m_i[r], rm);
            msafe[r] = fmaxf(m_new, -1e30f);
            alpha[r] = __expf(m_i[r] - msafe[r]);   // m_i=-inf -> 0
            m_i[r] = m_new;
            rowsum[r] = 0.f;
        }

        // P = exp(S - msafe), write to smem, rowsum
#pragma unroll
        for (int r = 0; r < 8; r++) {
#pragma unroll
            for (int c = 0; c < 4; c++) {
                float p = __expf(S[r][c] - msafe[r]);
                Ps[ty * 8 + r][tx * 4 + c] = p;
                rowsum[r] += p;
            }
#pragma unroll
            for (int off = 8; off >= 1; off >>= 1)
                rowsum[r] += __shfl_xor_sync(0xffffffffu, rowsum[r], off);
            l_i[r] = l_i[r] * alpha[r] + rowsum[r];
#pragma unroll
            for (int j = 0; j < 4; j++) O[r][j] *= alpha[r];
        }
        __syncthreads();   // Ps complete

        // O += Ps * Vs
#pragma unroll 4
        for (int k = 0; k < 64; k += 4) {
            float4 vf[4];
#pragma unroll
            for (int kk = 0; kk < 4; kk++) vf[kk] = *(const float4*)&Vs[k + kk][tx * 4];
#pragma unroll
            for (int r = 0; r < 8; r++) {
                float4 pf = *(const float4*)&Ps[ty * 8 + r][k];
                O[r][0] += pf.x * vf[0].x + pf.y * vf[1].x + pf.z * vf[2].x + pf.w * vf[3].x;
                O[r][1] += pf.x * vf[0].y + pf.y * vf[1].y + pf.z * vf[2].y + pf.w * vf[3].y;
                O[r][2] += pf.x * vf[0].z + pf.y * vf[1].z + pf.z * vf[2].z + pf.w * vf[3].z;
                O[r][3] += pf.x * vf[0].w + pf.y * vf[1].w + pf.z * vf[2].w + pf.w * vf[3].w;
            }
        }
        __syncthreads();   // before next tile overwrites Ks/Vs/Ms
    }

    // normalize + write out[b][l][h*64 + d]
#pragma unroll
    for (int r = 0; r < 8; r++) {
        float inv = 1.f / l_i[r];
        int l = q0 + ty * 8 + r;
        float4 v;
        v.x = O[r][0] * inv; v.y = O[r][1] * inv;
        v.z = O[r][2] * inv; v.w = O[r][3] * inv;
        *(float4*)(out + ((size_t)b_ * SEQ + l) * DM + h * HD + tx * 4) = v;
    }
}

// ================================ launch ===================================
extern "C" void kernel_launch(void* const* d_in, const int* in_sizes, int n_in,
                              void* d_out, int out_size)
{
    const float* q    = (const float*)d_in[0];
    const float* k    = (const float*)d_in[1];
    const float* v    = (const float*)d_in[2];
    const void*  mask = (const void*)d_in[3];
    const float* Wq = (const float*)d_in[4];
    const float* bq = (const float*)d_in[5];
    const float* Wk = (const float*)d_in[6];
    const float* bk = (const float*)d_in[7];
    const float* Wv = (const float*)d_in[8];
    const float* bv = (const float*)d_in[9];
    const float* Wo = (const float*)d_in[10];
    const float* bo = (const float*)d_in[11];

    float *pQ, *pK, *pV, *pA, *pM;
    cudaGetSymbolAddress((void**)&pQ, g_Q);
    cudaGetSymbolAddress((void**)&pK, g_K);
    cudaGetSymbolAddress((void**)&pV, g_V);
    cudaGetSymbolAddress((void**)&pA, g_attn);
    cudaGetSymbolAddress((void**)&pM, g_maskbias);

    mask_convert<<<1, 1024>>>(mask);

    dim3 ggrid(DM / GM_BN, MTOT / GM_BM);   // (8, 32)
    sgemm_abt<<<ggrid, 256>>>(q, Wq, bq, pQ, 1);
    sgemm_abt<<<ggrid, 256>>>(k, Wk, bk, pK, 1);
    sgemm_abt<<<ggrid, 256>>>(v, Wv, bv, pV, 1);

    dim3 agrid(SEQ / 64, BH);               // (32, 32)
    attn_kernel<<<agrid, 128>>>(pQ, pK, pV, pM, pA);

    sgemm_abt<<<ggrid, 256>>>(pA, Wo, bo, (float*)d_out, 0);
}

// round 10
// speedup vs baseline: 1.3815x; 1.3815x over previous
#include <cuda_runtime.h>
#include <cuda_bf16.h>
#include <math.h>
#include <stdint.h>

// Problem constants (fixed by setup_inputs)
#define BATCH   2
#define SEQ     2048
#define DM      1024
#define NH      16
#define HD      64
#define MTOT    (BATCH * SEQ)      // 4096
#define BH      (BATCH * NH)       // 32

// ---------------- scratch (static device globals; no allocs allowed) -------
__device__ float g_Q[(size_t)BH * SEQ * HD];     // [bh][l][hd]
__device__ float g_K[(size_t)BH * SEQ * HD];
__device__ float g_V[(size_t)BH * SEQ * HD];
__device__ float g_attn[(size_t)MTOT * DM];      // [b*l][dm]
__device__ float g_maskbias[MTOT];               // [b][l] -> 0 or -inf

// ======================= helpers ==========================================
__device__ __forceinline__ uint32_t smem_u32(const void* p) {
    uint32_t a;
    asm("{ .reg .u64 t; cvta.to.shared.u64 t, %1; cvt.u32.u64 %0, t; }"
        : "=r"(a) : "l"(p));
    return a;
}

// split fp32 -> (hi, lo) bf16x2 pairs
__device__ __forceinline__ void cvt2_split(float a, float b, uint32_t& h, uint32_t& l) {
    __nv_bfloat162 hh = __floats2bfloat162_rn(a, b);
    float ra = a - __bfloat162float(__low2bfloat16(hh));
    float rb = b - __bfloat162float(__high2bfloat16(hh));
    __nv_bfloat162 ll = __floats2bfloat162_rn(ra, rb);
    h = *reinterpret_cast<uint32_t*>(&hh);
    l = *reinterpret_cast<uint32_t*>(&ll);
}

#define LDMX4(r0, r1, r2, r3, addr)                                           \
    asm volatile("ldmatrix.sync.aligned.m8n8.x4.shared.b16 {%0,%1,%2,%3}, [%4];" \
        : "=r"(r0), "=r"(r1), "=r"(r2), "=r"(r3) : "r"(addr))

#define MMA16816(c, a, b)                                                     \
    asm volatile("mma.sync.aligned.m16n8k16.row.col.f32.bf16.bf16.f32 "       \
        "{%0,%1,%2,%3}, {%4,%5,%6,%7}, {%8,%9}, {%0,%1,%2,%3};"               \
        : "+f"((c)[0]), "+f"((c)[1]), "+f"((c)[2]), "+f"((c)[3])              \
        : "r"((a)[0]), "r"((a)[1]), "r"((a)[2]), "r"((a)[3]),                 \
          "r"((b)[0]), "r"((b)[1]))

// ================== mask dtype sniff + convert to float bias ===============
__global__ __launch_bounds__(1024) void mask_convert(const void* __restrict__ mask)
{
    __shared__ int s_f32, s_u8;
    const unsigned int* w = (const unsigned int*)mask;
    const int tid = threadIdx.x;
    if (tid == 0) { s_f32 = 0; s_u8 = 0; }
    __syncthreads();
    unsigned int x = w[tid];                 // words 0..1023
    if (x == 0x3F800000u) atomicOr(&s_f32, 1);
    else if (x > 1u)      atomicOr(&s_u8, 1);
    __syncthreads();
    const int cls = s_f32 ? 2 : (s_u8 ? 0 : 1);

#pragma unroll
    for (int u = 0; u < 4; u++) {
        int i = tid * 4 + u;                 // 0..4095
        bool m;
        if (cls == 0)      m = ((const unsigned char*)mask)[i] != 0;
        else if (cls == 1) m = ((const int*)mask)[i] != 0;
        else               m = ((const unsigned int*)mask)[i] != 0u;  // f32 bits
        g_maskbias[i] = m ? -INFINITY : 0.f;
    }
}

// ========== mma.sync GEMM: C = A * B^T + bias (split bf16, fp32 acc) =======
// A: [4096,1024] fp32 row-major. B: [1024,1024] fp32 row-major (W: [out,in]).
// CTA tile 128x128, BK=64, 8 warps, warp tile 64x32 (m16n8k16 micro-mma).
// 3 MMAs per product term: hi*hi + hi*lo + lo*hi (~16-bit effective mantissa).
#define BK     64
#define PADK   72        // bf16 elems per smem row (+8 pad: conflict-free ldmatrix)
#define TILEB  (128 * PADK * 2)              // bytes per operand buffer (18432)
#define OFF_AHI 0
#define OFF_ALO (TILEB)
#define OFF_BHI (2 * TILEB)
#define OFF_BLO (3 * TILEB)
#define GEMM_SMEM (4 * TILEB)                // 73728 B

__global__ __launch_bounds__(256) void gemm_mma(
    const float* __restrict__ A, const float* __restrict__ B,
    const float* __restrict__ bias, float* __restrict__ C, int permute)
{
    extern __shared__ char smem[];
    const uint32_t sb = smem_u32(smem);
    const int tid  = threadIdx.x;
    const int wid  = tid >> 5;
    const int lane = tid & 31;
    const int bm = blockIdx.y * 128;
    const int bn = blockIdx.x * 128;
    const int wm = (wid & 1) * 64;           // warp m-offset in CTA tile
    const int wn = (wid >> 1) * 32;          // warp n-offset

    float acc[4][4][4];                      // [mt][nt][c-frag]
#pragma unroll
    for (int i = 0; i < 4; i++)
#pragma unroll
        for (int j = 0; j < 4; j++)
#pragma unroll
            for (int c = 0; c < 4; c++) acc[i][j][c] = 0.f;

    // ldmatrix lane-address components
    const int lr  = lane & 7;
    const int l8  = (lane >> 3) & 1;
    const int l16 = (lane >> 4) & 1;

    for (int k0 = 0; k0 < DM; k0 += BK) {
        // ---- load fp32, split-convert, store bf16 tiles (128 x 64) ----
#pragma unroll
        for (int s = 0; s < 4; s++) {
            int g = tid + s * 256;           // 0..1023 groups of 8 elems
            int row = g >> 3;
            int c0  = (g & 7) * 8;
            uint32_t soff = (uint32_t)(row * PADK + c0) * 2;

            const float* pa = A + (size_t)(bm + row) * DM + k0 + c0;
            float4 u = *(const float4*)pa;
            float4 w = *(const float4*)(pa + 4);
            uint4 h4, l4;
            cvt2_split(u.x, u.y, h4.x, l4.x);
            cvt2_split(u.z, u.w, h4.y, l4.y);
            cvt2_split(w.x, w.y, h4.z, l4.z);
            cvt2_split(w.z, w.w, h4.w, l4.w);
            *(uint4*)(smem + OFF_AHI + soff) = h4;
            *(uint4*)(smem + OFF_ALO + soff) = l4;

            const float* pb = B + (size_t)(bn + row) * DM + k0 + c0;
            u = *(const float4*)pb;
            w = *(const float4*)(pb + 4);
            cvt2_split(u.x, u.y, h4.x, l4.x);
            cvt2_split(u.z, u.w, h4.y, l4.y);
            cvt2_split(w.x, w.y, h4.z, l4.z);
            cvt2_split(w.z, w.w, h4.w, l4.w);
            *(uint4*)(smem + OFF_BHI + soff) = h4;
            *(uint4*)(smem + OFF_BLO + soff) = l4;
        }
        __syncthreads();

        // ---- 4 k-steps of m16n8k16 ----
#pragma unroll
        for (int ks = 0; ks < 4; ks++) {
            uint32_t aH[4][4], aL[4][4];
#pragma unroll
            for (int mt = 0; mt < 4; mt++) {
                // A frag: rows (wm+mt*16) + lr + l8*8, cols ks*16 + l16*8
                uint32_t off = (uint32_t)((wm + mt * 16 + lr + l8 * 8) * PADK
                                          + ks * 16 + l16 * 8) * 2;
                LDMX4(aH[mt][0], aH[mt][1], aH[mt][2], aH[mt][3], sb + OFF_AHI + off);
                LDMX4(aL[mt][0], aL[mt][1], aL[mt][2], aL[mt][3], sb + OFF_ALO + off);
            }
            uint32_t bH[4][2], bL[4][2];
#pragma unroll
            for (int np = 0; np < 2; np++) {
                // B frag pair: rows n = (wn+np*16) + lr + l16*8, cols ks*16 + l8*8
                uint32_t off = (uint32_t)((wn + np * 16 + lr + l16 * 8) * PADK
                                          + ks * 16 + l8 * 8) * 2;
                uint32_t r0, r1, r2, r3;
                LDMX4(r0, r1, r2, r3, sb + OFF_BHI + off);
                bH[np * 2][0] = r0; bH[np * 2][1] = r1;
                bH[np * 2 + 1][0] = r2; bH[np * 2 + 1][1] = r3;
                LDMX4(r0, r1, r2, r3, sb + OFF_BLO + off);
                bL[np * 2][0] = r0; bL[np * 2][1] = r1;
                bL[np * 2 + 1][0] = r2; bL[np * 2 + 1][1] = r3;
            }
#pragma unroll
            for (int mt = 0; mt < 4; mt++)
#pragma unroll
                for (int nt = 0; nt < 4; nt++) {
                    MMA16816(acc[mt][nt], aH[mt], bH[nt]);
                    MMA16816(acc[mt][nt], aH[mt], bL[nt]);
                    MMA16816(acc[mt][nt], aL[mt], bH[nt]);
                }
        }
        __syncthreads();
    }

    // ---- epilogue: c-frag (row = l/4 [+8], col = (l%4)*2 [+1]) ----
    const int crow = lane >> 2;
    const int ccol = (lane & 3) * 2;
#pragma unroll
    for (int mt = 0; mt < 4; mt++) {
#pragma unroll
        for (int nt = 0; nt < 4; nt++) {
            int n0 = bn + wn + nt * 8 + ccol;
            float b0 = bias[n0], b1 = bias[n0 + 1];
#pragma unroll
            for (int half = 0; half < 2; half++) {
                int m = bm + wm + mt * 16 + crow + half * 8;
                float v0 = acc[mt][nt][half * 2 + 0] + b0;
                float v1 = acc[mt][nt][half * 2 + 1] + b1;
                float2 v; v.x = v0; v.y = v1;
                if (!permute) {
                    *(float2*)(C + (size_t)m * DM + n0) = v;
                } else {
                    int b_ = m >> 11;            // m / 2048
                    int l  = m & (SEQ - 1);
                    int h  = n0 >> 6;            // same head for n0, n0+1 (n0 even)
                    int d  = n0 & (HD - 1);
                    *(float2*)(C + ((size_t)(b_ * NH + h) * SEQ + l) * HD + d) = v;
                }
            }
        }
    }
}

// ======================= Flash attention (fp32) ============================
// Q,K,V: [bh][l][64]. out: [b][l][1024] (head-interleaved).
// grid: (SEQ/64, BH), 128 threads. Thread microtile: 8 q-rows x 4 kv-cols.
#define AT_PAD 68

__global__ __launch_bounds__(128) void attn_kernel(
    const float* __restrict__ Q, const float* __restrict__ K,
    const float* __restrict__ V, const float* __restrict__ maskbias,
    float* __restrict__ out)
{
    __shared__ float Qs[64][AT_PAD];
    __shared__ float Ks[64][AT_PAD];
    __shared__ float Vs[64][AT_PAD];
    __shared__ float Ps[64][AT_PAD];
    __shared__ float Ms[64];

    const int bh = blockIdx.y;
    const int b_ = bh >> 4;
    const int h  = bh & (NH - 1);
    const int q0 = blockIdx.x * 64;
    const int tid = threadIdx.x;
    const int tx = tid & 15;   // col group (4 cols)
    const int ty = tid >> 4;   // row group (8 rows)
    const float scale = 0.125f;   // 1/sqrt(64)

    // load Q tile (64x64)
    const float* Qb = Q + ((size_t)bh * SEQ + q0) * HD;
    for (int i = tid; i < 64 * 64; i += 128) Qs[i >> 6][i & 63] = Qb[i];

    float O[8][4];
    float m_i[8], l_i[8];
#pragma unroll
    for (int r = 0; r < 8; r++) {
        m_i[r] = -INFINITY; l_i[r] = 0.f;
#pragma unroll
        for (int j = 0; j < 4; j++) O[r][j] = 0.f;
    }
    __syncthreads();

    for (int t = 0; t < SEQ / 64; t++) {
        const int k0 = t * 64;
        const float* Kb = K + ((size_t)bh * SEQ + k0) * HD;
        const float* Vb = V + ((size_t)bh * SEQ + k0) * HD;
        for (int i = tid; i < 64 * 64; i += 128) {
            Ks[i >> 6][i & 63] = Kb[i];
            Vs[i >> 6][i & 63] = Vb[i];
        }
        if (tid < 64) Ms[tid] = maskbias[(size_t)b_ * SEQ + k0 + tid];
        __syncthreads();

        // S = Qs * Ks^T (8x4 per thread)
        float S[8][4];
#pragma unroll
        for (int r = 0; r < 8; r++)
#pragma unroll
            for (int c = 0; c < 4; c++) S[r][c] = 0.f;

#pragma unroll 4
        for (int d = 0; d < HD; d += 4) {
            float4 kf[4];
#pragma unroll
            for (int c = 0; c < 4; c++) kf[c] = *(const float4*)&Ks[tx * 4 + c][d];
#pragma unroll
            for (int r = 0; r < 8; r++) {
                float4 qf = *(const float4*)&Qs[ty * 8 + r][d];
#pragma unroll
                for (int c = 0; c < 4; c++) {
                    S[r][c] += qf.x * kf[c].x + qf.y * kf[c].y
                             + qf.z * kf[c].z + qf.w * kf[c].w;
                }
            }
        }

        // scale + mask, rowmax over the 16-lane (tx) group
        float msafe[8], alpha[8], rowsum[8];
#pragma unroll
        for (int r = 0; r < 8; r++) {
            float rm = -INFINITY;
#pragma unroll
            for (int c = 0; c < 4; c++) {
                S[r][c] = S[r][c] * scale + Ms[tx * 4 + c];
                rm = fmaxf(rm, S[r][c]);
            }
#pragma unroll
            for (int off = 8; off >= 1; off >>= 1)
                rm = fmaxf(rm, __shfl_xor_sync(0xffffffffu, rm, off));
            float m_new = fmaxf(m_i[r], rm);
            msafe[r] = fmaxf(m_new, -1e30f);
            alpha[r] = __expf(m_i[r] - msafe[r]);   // m_i=-inf -> 0
            m_i[r] = m_new;
            rowsum[r] = 0.f;
        }

        // P = exp(S - msafe), write to smem, rowsum
#pragma unroll
        for (int r = 0; r < 8; r++) {
#pragma unroll
            for (int c = 0; c < 4; c++) {
                float p = __expf(S[r][c] - msafe[r]);
                Ps[ty * 8 + r][tx * 4 + c] = p;
                rowsum[r] += p;
            }
#pragma unroll
            for (int off = 8; off >= 1; off >>= 1)
                rowsum[r] += __shfl_xor_sync(0xffffffffu, rowsum[r], off);
            l_i[r] = l_i[r] * alpha[r] + rowsum[r];
#pragma unroll
            for (int j = 0; j < 4; j++) O[r][j] *= alpha[r];
        }
        __syncthreads();   // Ps complete

        // O += Ps * Vs
#pragma unroll 4
        for (int k = 0; k < 64; k += 4) {
            float4 vf[4];
#pragma unroll
            for (int kk = 0; kk < 4; kk++) vf[kk] = *(const float4*)&Vs[k + kk][tx * 4];
#pragma unroll
            for (int r = 0; r < 8; r++) {
                float4 pf = *(const float4*)&Ps[ty * 8 + r][k];
                O[r][0] += pf.x * vf[0].x + pf.y * vf[1].x + pf.z * vf[2].x + pf.w * vf[3].x;
                O[r][1] += pf.x * vf[0].y + pf.y * vf[1].y + pf.z * vf[2].y + pf.w * vf[3].y;
                O[r][2] += pf.x * vf[0].z + pf.y * vf[1].z + pf.z * vf[2].z + pf.w * vf[3].z;
                O[r][3] += pf.x * vf[0].w + pf.y * vf[1].w + pf.z * vf[2].w + pf.w * vf[3].w;
            }
        }
        __syncthreads();   // before next tile overwrites Ks/Vs/Ms
    }

    // normalize + write out[b][l][h*64 + d]
#pragma unroll
    for (int r = 0; r < 8; r++) {
        float inv = 1.f / l_i[r];
        int l = q0 + ty * 8 + r;
        float4 v;
        v.x = O[r][0] * inv; v.y = O[r][1] * inv;
        v.z = O[r][2] * inv; v.w = O[r][3] * inv;
        *(float4*)(out + ((size_t)b_ * SEQ + l) * DM + h * HD + tx * 4) = v;
    }
}

// ================================ launch ===================================
extern "C" void kernel_launch(void* const* d_in, const int* in_sizes, int n_in,
                              void* d_out, int out_size)
{
    const float* q    = (const float*)d_in[0];
    const float* k    = (const float*)d_in[1];
    const float* v    = (const float*)d_in[2];
    const void*  mask = (const void*)d_in[3];
    const float* Wq = (const float*)d_in[4];
    const float* bq = (const float*)d_in[5];
    const float* Wk = (const float*)d_in[6];
    const float* bk = (const float*)d_in[7];
    const float* Wv = (const float*)d_in[8];
    const float* bv = (const float*)d_in[9];
    const float* Wo = (const float*)d_in[10];
    const float* bo = (const float*)d_in[11];

    float *pQ, *pK, *pV, *pA, *pM;
    cudaGetSymbolAddress((void**)&pQ, g_Q);
    cudaGetSymbolAddress((void**)&pK, g_K);
    cudaGetSymbolAddress((void**)&pV, g_V);
    cudaGetSymbolAddress((void**)&pA, g_attn);
    cudaGetSymbolAddress((void**)&pM, g_maskbias);

    cudaFuncSetAttribute(gemm_mma, cudaFuncAttributeMaxDynamicSharedMemorySize,
                         GEMM_SMEM);

    mask_convert<<<1, 1024>>>(mask);

    dim3 ggrid(DM / 128, MTOT / 128);       // (8, 32)
    gemm_mma<<<ggrid, 256, GEMM_SMEM>>>(q, Wq, bq, pQ, 1);
    gemm_mma<<<ggrid, 256, GEMM_SMEM>>>(k, Wk, bk, pK, 1);
    gemm_mma<<<ggrid, 256, GEMM_SMEM>>>(v, Wv, bv, pV, 1);

    dim3 agrid(SEQ / 64, BH);               // (32, 32)
    attn_kernel<<<agrid, 128>>>(pQ, pK, pV, pM, pA);

    gemm_mma<<<ggrid, 256, GEMM_SMEM>>>(pA, Wo, bo, (float*)d_out, 0);
}

// round 11
// speedup vs baseline: 3.6501x; 2.6421x over previous
#include <cuda_runtime.h>
#include <cuda_bf16.h>
#include <math.h>
#include <stdint.h>

// Problem constants (fixed by setup_inputs)
#define BATCH   2
#define SEQ     2048
#define DM      1024
#define NH      16
#define HD      64
#define MTOT    (BATCH * SEQ)      // 4096
#define BH      (BATCH * NH)       // 32

// ---------------- scratch (static device globals; no allocs allowed) -------
__device__ float g_Q[(size_t)BH * SEQ * HD];     // [bh][l][hd]
__device__ float g_K[(size_t)BH * SEQ * HD];
__device__ float g_V[(size_t)BH * SEQ * HD];
__device__ float g_attn[(size_t)MTOT * DM];      // [b*l][dm]
__device__ float g_maskbias[MTOT];               // [b][l] -> 0 or -inf

// ======================= helpers ==========================================
__device__ __forceinline__ uint32_t smem_u32(const void* p) {
    uint32_t a;
    asm("{ .reg .u64 t; cvta.to.shared.u64 t, %1; cvt.u32.u64 %0, t; }"
        : "=r"(a) : "l"(p));
    return a;
}

// split fp32 -> (hi, lo) bf16x2 pairs
__device__ __forceinline__ void cvt2_split(float a, float b, uint32_t& h, uint32_t& l) {
    __nv_bfloat162 hh = __floats2bfloat162_rn(a, b);
    float ra = a - __bfloat162float(__low2bfloat16(hh));
    float rb = b - __bfloat162float(__high2bfloat16(hh));
    __nv_bfloat162 ll = __floats2bfloat162_rn(ra, rb);
    h = *reinterpret_cast<uint32_t*>(&hh);
    l = *reinterpret_cast<uint32_t*>(&ll);
}

#define LDMX4(r0, r1, r2, r3, addr)                                           \
    asm volatile("ldmatrix.sync.aligned.m8n8.x4.shared.b16 {%0,%1,%2,%3}, [%4];" \
        : "=r"(r0), "=r"(r1), "=r"(r2), "=r"(r3) : "r"(addr))

#define LDMX4T(r0, r1, r2, r3, addr)                                          \
    asm volatile("ldmatrix.sync.aligned.m8n8.x4.trans.shared.b16 {%0,%1,%2,%3}, [%4];" \
        : "=r"(r0), "=r"(r1), "=r"(r2), "=r"(r3) : "r"(addr))

#define MMA16816(c, a, b)                                                     \
    asm volatile("mma.sync.aligned.m16n8k16.row.col.f32.bf16.bf16.f32 "       \
        "{%0,%1,%2,%3}, {%4,%5,%6,%7}, {%8,%9}, {%0,%1,%2,%3};"               \
        : "+f"((c)[0]), "+f"((c)[1]), "+f"((c)[2]), "+f"((c)[3])              \
        : "r"((a)[0]), "r"((a)[1]), "r"((a)[2]), "r"((a)[3]),                 \
          "r"((b)[0]), "r"((b)[1]))

// ================== mask dtype sniff + convert to float bias ===============
__global__ __launch_bounds__(1024) void mask_convert(const void* __restrict__ mask)
{
    __shared__ int s_f32, s_u8;
    const unsigned int* w = (const unsigned int*)mask;
    const int tid = threadIdx.x;
    if (tid == 0) { s_f32 = 0; s_u8 = 0; }
    __syncthreads();
    unsigned int x = w[tid];                 // words 0..1023
    if (x == 0x3F800000u) atomicOr(&s_f32, 1);
    else if (x > 1u)      atomicOr(&s_u8, 1);
    __syncthreads();
    const int cls = s_f32 ? 2 : (s_u8 ? 0 : 1);

#pragma unroll
    for (int u = 0; u < 4; u++) {
        int i = tid * 4 + u;                 // 0..4095
        bool m;
        if (cls == 0)      m = ((const unsigned char*)mask)[i] != 0;
        else if (cls == 1) m = ((const int*)mask)[i] != 0;
        else               m = ((const unsigned int*)mask)[i] != 0u;  // f32 bits
        g_maskbias[i] = m ? -INFINITY : 0.f;
    }
}

// ========== mma.sync GEMM: C = A * B^T + bias (split bf16, fp32 acc) =======
#define BK     64
#define PADK   72        // bf16 elems per smem row (+8 pad: conflict-free ldmatrix)
#define TILEB  (128 * PADK * 2)              // bytes per operand buffer (18432)
#define OFF_AHI 0
#define OFF_ALO (TILEB)
#define OFF_BHI (2 * TILEB)
#define OFF_BLO (3 * TILEB)
#define GEMM_SMEM (4 * TILEB)                // 73728 B

__global__ __launch_bounds__(256) void gemm_mma(
    const float* __restrict__ A, const float* __restrict__ B,
    const float* __restrict__ bias, float* __restrict__ C, int permute)
{
    extern __shared__ char smem[];
    const uint32_t sb = smem_u32(smem);
    const int tid  = threadIdx.x;
    const int wid  = tid >> 5;
    const int lane = tid & 31;
    const int bm = blockIdx.y * 128;
    const int bn = blockIdx.x * 128;
    const int wm = (wid & 1) * 64;           // warp m-offset in CTA tile
    const int wn = (wid >> 1) * 32;          // warp n-offset

    float acc[4][4][4];                      // [mt][nt][c-frag]
#pragma unroll
    for (int i = 0; i < 4; i++)
#pragma unroll
        for (int j = 0; j < 4; j++)
#pragma unroll
            for (int c = 0; c < 4; c++) acc[i][j][c] = 0.f;

    const int lr  = lane & 7;
    const int l8  = (lane >> 3) & 1;
    const int l16 = (lane >> 4) & 1;

    for (int k0 = 0; k0 < DM; k0 += BK) {
#pragma unroll
        for (int s = 0; s < 4; s++) {
            int g = tid + s * 256;           // 0..1023 groups of 8 elems
            int row = g >> 3;
            int c0  = (g & 7) * 8;
            uint32_t soff = (uint32_t)(row * PADK + c0) * 2;

            const float* pa = A + (size_t)(bm + row) * DM + k0 + c0;
            float4 u = *(const float4*)pa;
            float4 w = *(const float4*)(pa + 4);
            uint4 h4, l4;
            cvt2_split(u.x, u.y, h4.x, l4.x);
            cvt2_split(u.z, u.w, h4.y, l4.y);
            cvt2_split(w.x, w.y, h4.z, l4.z);
            cvt2_split(w.z, w.w, h4.w, l4.w);
            *(uint4*)(smem + OFF_AHI + soff) = h4;
            *(uint4*)(smem + OFF_ALO + soff) = l4;

            const float* pb = B + (size_t)(bn + row) * DM + k0 + c0;
            u = *(const float4*)pb;
            w = *(const float4*)(pb + 4);
            cvt2_split(u.x, u.y, h4.x, l4.x);
            cvt2_split(u.z, u.w, h4.y, l4.y);
            cvt2_split(w.x, w.y, h4.z, l4.z);
            cvt2_split(w.z, w.w, h4.w, l4.w);
            *(uint4*)(smem + OFF_BHI + soff) = h4;
            *(uint4*)(smem + OFF_BLO + soff) = l4;
        }
        __syncthreads();

#pragma unroll
        for (int ks = 0; ks < 4; ks++) {
            uint32_t aH[4][4], aL[4][4];
#pragma unroll
            for (int mt = 0; mt < 4; mt++) {
                uint32_t off = (uint32_t)((wm + mt * 16 + lr + l8 * 8) * PADK
                                          + ks * 16 + l16 * 8) * 2;
                LDMX4(aH[mt][0], aH[mt][1], aH[mt][2], aH[mt][3], sb + OFF_AHI + off);
                LDMX4(aL[mt][0], aL[mt][1], aL[mt][2], aL[mt][3], sb + OFF_ALO + off);
            }
            uint32_t bH[4][2], bL[4][2];
#pragma unroll
            for (int np = 0; np < 2; np++) {
                uint32_t off = (uint32_t)((wn + np * 16 + lr + l16 * 8) * PADK
                                          + ks * 16 + l8 * 8) * 2;
                uint32_t r0, r1, r2, r3;
                LDMX4(r0, r1, r2, r3, sb + OFF_BHI + off);
                bH[np * 2][0] = r0; bH[np * 2][1] = r1;
                bH[np * 2 + 1][0] = r2; bH[np * 2 + 1][1] = r3;
                LDMX4(r0, r1, r2, r3, sb + OFF_BLO + off);
                bL[np * 2][0] = r0; bL[np * 2][1] = r1;
                bL[np * 2 + 1][0] = r2; bL[np * 2 + 1][1] = r3;
            }
#pragma unroll
            for (int mt = 0; mt < 4; mt++)
#pragma unroll
                for (int nt = 0; nt < 4; nt++) {
                    MMA16816(acc[mt][nt], aH[mt], bH[nt]);
                    MMA16816(acc[mt][nt], aH[mt], bL[nt]);
                    MMA16816(acc[mt][nt], aL[mt], bH[nt]);
                }
        }
        __syncthreads();
    }

    const int crow = lane >> 2;
    const int ccol = (lane & 3) * 2;
#pragma unroll
    for (int mt = 0; mt < 4; mt++) {
#pragma unroll
        for (int nt = 0; nt < 4; nt++) {
            int n0 = bn + wn + nt * 8 + ccol;
            float b0 = bias[n0], b1 = bias[n0 + 1];
#pragma unroll
            for (int half = 0; half < 2; half++) {
                int m = bm + wm + mt * 16 + crow + half * 8;
                float v0 = acc[mt][nt][half * 2 + 0] + b0;
                float v1 = acc[mt][nt][half * 2 + 1] + b1;
                float2 v; v.x = v0; v.y = v1;
                if (!permute) {
                    *(float2*)(C + (size_t)m * DM + n0) = v;
                } else {
                    int b_ = m >> 11;            // m / 2048
                    int l  = m & (SEQ - 1);
                    int h  = n0 >> 6;            // same head for n0, n0+1 (n0 even)
                    int d  = n0 & (HD - 1);
                    *(float2*)(C + ((size_t)(b_ * NH + h) * SEQ + l) * HD + d) = v;
                }
            }
        }
    }
}

// ============== Flash attention on mma.sync (split bf16) ===================
// Q,K,V: [bh][l][64]. out: [b][l][1024]. BM=64 q-rows/CTA, BN=64 kv/tile.
// 4 warps: warp w owns q-rows [w*16, w*16+16). All GEMM fragments split hi/lo
// (3 MMAs per product). P fragments built directly from S accumulators.
#define APAD  72
#define ATILE (64 * APAD * 2)      // 9216 B per operand buffer
#define A_QH  0
#define A_QL  (ATILE)
#define A_KH  (2 * ATILE)
#define A_KL  (3 * ATILE)
#define A_VH  (4 * ATILE)
#define A_VL  (5 * ATILE)
#define A_MS  (6 * ATILE)          // 64 floats
#define ATT_SMEM (A_MS + 256)      // 55552 B

__global__ __launch_bounds__(128) void attn_mma(
    const float* __restrict__ Q, const float* __restrict__ K,
    const float* __restrict__ V, const float* __restrict__ maskbias,
    float* __restrict__ out)
{
    extern __shared__ char smem[];
    const uint32_t sb = smem_u32(smem);
    float* Ms = (float*)(smem + A_MS);

    const int bh = blockIdx.y;
    const int b_ = bh >> 4;
    const int h  = bh & (NH - 1);
    const int q0 = blockIdx.x * 64;
    const int tid  = threadIdx.x;
    const int wid  = tid >> 5;
    const int lane = tid & 31;
    const int lr  = lane & 7;
    const int l8  = (lane >> 3) & 1;
    const int l16 = (lane >> 4) & 1;
    const int crow = lane >> 2;
    const int ccol = (lane & 3) * 2;
    const float scale = 0.125f;              // 1/sqrt(64)

    // ---- load + split Q tile (64 x 64) once ----
    const float* Qb = Q + ((size_t)bh * SEQ + q0) * HD;
#pragma unroll
    for (int s = 0; s < 8; s++) {
        int g = tid + s * 128;               // 0..1023 float4 groups
        int row = g >> 4;
        int c0  = (g & 15) * 4;
        float4 u = *(const float4*)(Qb + row * HD + c0);
        uint2 hv, lv;
        cvt2_split(u.x, u.y, hv.x, lv.x);
        cvt2_split(u.z, u.w, hv.y, lv.y);
        uint32_t soff = (uint32_t)(row * APAD + c0) * 2;
        *(uint2*)(smem + A_QH + soff) = hv;
        *(uint2*)(smem + A_QL + soff) = lv;
    }

    float O[8][4];
#pragma unroll
    for (int i = 0; i < 8; i++)
#pragma unroll
        for (int j = 0; j < 4; j++) O[i][j] = 0.f;
    float m0 = -INFINITY, m1 = -INFINITY, li0 = 0.f, li1 = 0.f;
    __syncthreads();

    for (int t = 0; t < SEQ / 64; t++) {
        const int k0 = t * 64;
        // ---- load + split K, V tiles ----
        const float* Kb = K + ((size_t)bh * SEQ + k0) * HD;
        const float* Vb = V + ((size_t)bh * SEQ + k0) * HD;
#pragma unroll
        for (int s = 0; s < 8; s++) {
            int g = tid + s * 128;
            int row = g >> 4;
            int c0  = (g & 15) * 4;
            uint32_t soff = (uint32_t)(row * APAD + c0) * 2;
            float4 u = *(const float4*)(Kb + row * HD + c0);
            uint2 hv, lv;
            cvt2_split(u.x, u.y, hv.x, lv.x);
            cvt2_split(u.z, u.w, hv.y, lv.y);
            *(uint2*)(smem + A_KH + soff) = hv;
            *(uint2*)(smem + A_KL + soff) = lv;
            u = *(const float4*)(Vb + row * HD + c0);
            cvt2_split(u.x, u.y, hv.x, lv.x);
            cvt2_split(u.z, u.w, hv.y, lv.y);
            *(uint2*)(smem + A_VH + soff) = hv;
            *(uint2*)(smem + A_VL + soff) = lv;
        }
        if (tid < 64) Ms[tid] = maskbias[(size_t)b_ * SEQ + k0 + tid];
        __syncthreads();

        // ---- S = Q * K^T (warp: 16 q-rows x 64 kv) ----
        float S[8][4];
#pragma unroll
        for (int i = 0; i < 8; i++)
#pragma unroll
            for (int j = 0; j < 4; j++) S[i][j] = 0.f;

#pragma unroll
        for (int ks = 0; ks < 4; ks++) {
            uint32_t aH[4], aL[4];
            uint32_t offa = (uint32_t)((wid * 16 + lr + l8 * 8) * APAD
                                       + ks * 16 + l16 * 8) * 2;
            LDMX4(aH[0], aH[1], aH[2], aH[3], sb + A_QH + offa);
            LDMX4(aL[0], aL[1], aL[2], aL[3], sb + A_QL + offa);
            uint32_t bH[8][2], bL[8][2];
#pragma unroll
            for (int np = 0; np < 4; np++) {
                uint32_t offb = (uint32_t)((np * 16 + lr + l16 * 8) * APAD
                                           + ks * 16 + l8 * 8) * 2;
                uint32_t r0, r1, r2, r3;
                LDMX4(r0, r1, r2, r3, sb + A_KH + offb);
                bH[np * 2][0] = r0; bH[np * 2][1] = r1;
                bH[np * 2 + 1][0] = r2; bH[np * 2 + 1][1] = r3;
                LDMX4(r0, r1, r2, r3, sb + A_KL + offb);
                bL[np * 2][0] = r0; bL[np * 2][1] = r1;
                bL[np * 2 + 1][0] = r2; bL[np * 2 + 1][1] = r3;
            }
#pragma unroll
            for (int nt = 0; nt < 8; nt++) {
                MMA16816(S[nt], aH, bH[nt]);
                MMA16816(S[nt], aH, bL[nt]);
                MMA16816(S[nt], aL, bH[nt]);
            }
        }

        // ---- softmax (rows crow / crow+8 of this warp's 16) ----
        float rm0 = -INFINITY, rm1 = -INFINITY;
#pragma unroll
        for (int nt = 0; nt < 8; nt++) {
            float mk0 = Ms[nt * 8 + ccol], mk1 = Ms[nt * 8 + ccol + 1];
            S[nt][0] = S[nt][0] * scale + mk0;
            S[nt][1] = S[nt][1] * scale + mk1;
            S[nt][2] = S[nt][2] * scale + mk0;
            S[nt][3] = S[nt][3] * scale + mk1;
            rm0 = fmaxf(rm0, fmaxf(S[nt][0], S[nt][1]));
            rm1 = fmaxf(rm1, fmaxf(S[nt][2], S[nt][3]));
        }
        rm0 = fmaxf(rm0, __shfl_xor_sync(0xffffffffu, rm0, 1));
        rm0 = fmaxf(rm0, __shfl_xor_sync(0xffffffffu, rm0, 2));
        rm1 = fmaxf(rm1, __shfl_xor_sync(0xffffffffu, rm1, 1));
        rm1 = fmaxf(rm1, __shfl_xor_sync(0xffffffffu, rm1, 2));

        float mn0 = fmaxf(m0, rm0), mn1 = fmaxf(m1, rm1);
        float ms0 = fmaxf(mn0, -1e30f), ms1 = fmaxf(mn1, -1e30f);
        float al0 = __expf(m0 - ms0), al1 = __expf(m1 - ms1);
        m0 = mn0; m1 = mn1;

        float rs0 = 0.f, rs1 = 0.f;
        uint32_t pH[4][4], pL[4][4];         // A-frags for PV, [kv chunk][reg]
#pragma unroll
        for (int nt = 0; nt < 8; nt++) {
            float p0 = __expf(S[nt][0] - ms0);
            float p1 = __expf(S[nt][1] - ms0);
            float p2 = __expf(S[nt][2] - ms1);
            float p3 = __expf(S[nt][3] - ms1);
            rs0 += p0 + p1; rs1 += p2 + p3;
            int ks2 = nt >> 1, base = (nt & 1) * 2;
            uint32_t h01, l01, h23, l23;
            cvt2_split(p0, p1, h01, l01);
            cvt2_split(p2, p3, h23, l23);
            pH[ks2][base] = h01; pH[ks2][base + 1] = h23;
            pL[ks2][base] = l01; pL[ks2][base + 1] = l23;
        }
        rs0 += __shfl_xor_sync(0xffffffffu, rs0, 1);
        rs0 += __shfl_xor_sync(0xffffffffu, rs0, 2);
        rs1 += __shfl_xor_sync(0xffffffffu, rs1, 1);
        rs1 += __shfl_xor_sync(0xffffffffu, rs1, 2);
        li0 = li0 * al0 + rs0;
        li1 = li1 * al1 + rs1;
#pragma unroll
        for (int nt = 0; nt < 8; nt++) {
            O[nt][0] *= al0; O[nt][1] *= al0;
            O[nt][2] *= al1; O[nt][3] *= al1;
        }

        // ---- O += P * V (V via ldmatrix.trans) ----
#pragma unroll
        for (int ks2 = 0; ks2 < 4; ks2++) {
            uint32_t bH2[8][2], bL2[8][2];
#pragma unroll
            for (int np = 0; np < 4; np++) {
                uint32_t offv = (uint32_t)((ks2 * 16 + lr + l8 * 8) * APAD
                                           + np * 16 + l16 * 8) * 2;
                uint32_t r0, r1, r2, r3;
                LDMX4T(r0, r1, r2, r3, sb + A_VH + offv);
                bH2[np * 2][0] = r0; bH2[np * 2][1] = r1;
                bH2[np * 2 + 1][0] = r2; bH2[np * 2 + 1][1] = r3;
                LDMX4T(r0, r1, r2, r3, sb + A_VL + offv);
                bL2[np * 2][0] = r0; bL2[np * 2][1] = r1;
                bL2[np * 2 + 1][0] = r2; bL2[np * 2 + 1][1] = r3;
            }
#pragma unroll
            for (int nt = 0; nt < 8; nt++) {
                MMA16816(O[nt], pH[ks2], bH2[nt]);
                MMA16816(O[nt], pH[ks2], bL2[nt]);
                MMA16816(O[nt], pL[ks2], bH2[nt]);
            }
        }
        __syncthreads();   // before next tile overwrites K/V/Ms
    }

    // ---- normalize + write out[b][l][h*64 + d] ----
    float inv0 = 1.f / li0, inv1 = 1.f / li1;
    int l0 = q0 + wid * 16 + crow;
    float* o0 = out + ((size_t)b_ * SEQ + l0) * DM + h * HD;
    float* o1 = o0 + (size_t)8 * DM;
#pragma unroll
    for (int nt = 0; nt < 8; nt++) {
        int col = nt * 8 + ccol;
        float2 v0; v0.x = O[nt][0] * inv0; v0.y = O[nt][1] * inv0;
        float2 v1; v1.x = O[nt][2] * inv1; v1.y = O[nt][3] * inv1;
        *(float2*)(o0 + col) = v0;
        *(float2*)(o1 + col) = v1;
    }
}

// ================================ launch ===================================
extern "C" void kernel_launch(void* const* d_in, const int* in_sizes, int n_in,
                              void* d_out, int out_size)
{
    const float* q    = (const float*)d_in[0];
    const float* k    = (const float*)d_in[1];
    const float* v    = (const float*)d_in[2];
    const void*  mask = (const void*)d_in[3];
    const float* Wq = (const float*)d_in[4];
    const float* bq = (const float*)d_in[5];
    const float* Wk = (const float*)d_in[6];
    const float* bk = (const float*)d_in[7];
    const float* Wv = (const float*)d_in[8];
    const float* bv = (const float*)d_in[9];
    const float* Wo = (const float*)d_in[10];
    const float* bo = (const float*)d_in[11];

    float *pQ, *pK, *pV, *pA, *pM;
    cudaGetSymbolAddress((void**)&pQ, g_Q);
    cudaGetSymbolAddress((void**)&pK, g_K);
    cudaGetSymbolAddress((void**)&pV, g_V);
    cudaGetSymbolAddress((void**)&pA, g_attn);
    cudaGetSymbolAddress((void**)&pM, g_maskbias);

    cudaFuncSetAttribute(gemm_mma, cudaFuncAttributeMaxDynamicSharedMemorySize,
                         GEMM_SMEM);
    cudaFuncSetAttribute(attn_mma, cudaFuncAttributeMaxDynamicSharedMemorySize,
                         ATT_SMEM);

    mask_convert<<<1, 1024>>>(mask);

    dim3 ggrid(DM / 128, MTOT / 128);       // (8, 32)
    gemm_mma<<<ggrid, 256, GEMM_SMEM>>>(q, Wq, bq, pQ, 1);
    gemm_mma<<<ggrid, 256, GEMM_SMEM>>>(k, Wk, bk, pK, 1);
    gemm_mma<<<ggrid, 256, GEMM_SMEM>>>(v, Wv, bv, pV, 1);

    dim3 agrid(SEQ / 64, BH);               // (32, 32)
    attn_mma<<<agrid, 128, ATT_SMEM>>>(pQ, pK, pV, pM, pA);

    gemm_mma<<<ggrid, 256, GEMM_SMEM>>>(pA, Wo, bo, (float*)d_out, 0);
}